// round 7
// baseline (speedup 1.0000x reference)
#include <cuda_runtime.h>
#include <cfloat>
#include <cstdint>

// Problem: x [65536, 256] fp32, codebook [1024, 256] fp32. Nearest code per row.
#define N_ROWS  65536
#define DIM     256
#define KCODES  1024
#define RN      128     // rows per CTA
#define CN      128     // codes per chunk
#define NCHUNK  (KCODES / CN)
#define KS      16      // dims per stage
#define NST     (DIM / KS)
#define NTHREADS 512

// smem byte offsets (each tile region: 2 buffers x 8192B)
#define OFF_AH     0
#define OFF_AL     16384
#define OFF_BH     32768
#define OFF_BL     49152
#define OFF_SNORM  65536
#define OFF_SREDV  69632
#define OFF_SREDI  71680
#define OFF_SIDX   73728
#define SMEM_BYTES 74240
#define BUFSTRIDE  8192

__device__ float    g_enorm[KCODES];
__device__ uint32_t g_xh[N_ROWS * DIM];     // pre-split tf32 hi of x
__device__ uint32_t g_xl[N_ROWS * DIM];     // pre-split tf32 lo of x
__device__ uint32_t g_cbh[KCODES * DIM];
__device__ uint32_t g_cbl[KCODES * DIM];

__device__ __forceinline__ uint32_t smem_u32(const void* p) {
    uint32_t a;
    asm("{ .reg .u64 t; cvta.to.shared.u64 t, %1; cvt.u32.u64 %0, t; }" : "=r"(a) : "l"(p));
    return a;
}

__device__ __forceinline__ void split1(float v, uint32_t& h, uint32_t& l) {
    uint32_t hb; asm("cvt.rna.tf32.f32 %0, %1;" : "=r"(hb) : "f"(v));
    float lf = v - __uint_as_float(hb);
    uint32_t lb; asm("cvt.rna.tf32.f32 %0, %1;" : "=r"(lb) : "f"(lf));
    h = hb; l = lb;
}
__device__ __forceinline__ void split4(float4 v, uint4& h, uint4& l) {
    split1(v.x, h.x, l.x); split1(v.y, h.y, l.y);
    split1(v.z, h.z, l.z); split1(v.w, h.w, l.w);
}

__device__ __forceinline__ void ldm4(uint32_t* r, uint32_t addr) {
    asm volatile("ldmatrix.sync.aligned.m8n8.x4.shared.b16 {%0,%1,%2,%3}, [%4];"
                 : "=r"(r[0]), "=r"(r[1]), "=r"(r[2]), "=r"(r[3]) : "r"(addr));
}

__device__ __forceinline__ void mma8(float* c, const uint32_t* a, uint32_t b0, uint32_t b1) {
    asm volatile(
        "mma.sync.aligned.m16n8k8.row.col.f32.tf32.tf32.f32 "
        "{%0,%1,%2,%3}, {%4,%5,%6,%7}, {%8,%9}, {%0,%1,%2,%3};"
        : "+f"(c[0]), "+f"(c[1]), "+f"(c[2]), "+f"(c[3])
        : "r"(a[0]), "r"(a[1]), "r"(a[2]), "r"(a[3]), "r"(b0), "r"(b1));
}

// --- pre-kernels: split to tf32 hi/lo, compute codebook norms ---
__global__ void prep_x_kernel(const float* __restrict__ x) {
    const int i = blockIdx.x * 256 + threadIdx.x;       // float4 index, 4.19M total
    const float4 v = reinterpret_cast<const float4*>(x)[i];
    uint4 h, l; split4(v, h, l);
    reinterpret_cast<uint4*>(g_xh)[i] = h;
    reinterpret_cast<uint4*>(g_xl)[i] = l;
}

__global__ void prep_cb_kernel(const float* __restrict__ cb) {
    const int code = blockIdx.x;
    const int t = threadIdx.x;                          // 64 threads, one float4 each
    const int i = code * (DIM / 4) + t;
    const float4 v = reinterpret_cast<const float4*>(cb)[i];
    uint4 h, l; split4(v, h, l);
    reinterpret_cast<uint4*>(g_cbh)[i] = h;
    reinterpret_cast<uint4*>(g_cbl)[i] = l;
    float s = v.x * v.x + v.y * v.y + v.z * v.z + v.w * v.w;
    #pragma unroll
    for (int o = 16; o > 0; o >>= 1) s += __shfl_down_sync(0xffffffffu, s, o);
    __shared__ float ws[2];
    if ((t & 31) == 0) ws[t >> 5] = s;
    __syncthreads();
    if (t == 0) g_enorm[code] = ws[0] + ws[1];
}

// --- main kernel ---
__global__ __launch_bounds__(NTHREADS, 1)
void vq_kernel(const float* __restrict__ cb,
               float* __restrict__ outq, float* __restrict__ outidx, int has_idx)
{
    extern __shared__ char sm[];
    const uint32_t sb = smem_u32(sm);
    const int tid  = threadIdx.x;
    const int lane = tid & 31;
    const int wid  = tid >> 5;       // 0..15
    const int wm   = wid & 3;        // rows wm*32..+31
    const int wn   = wid >> 2;       // codes wn*32..+31 within chunk
    const int r0   = blockIdx.x * RN;

    float* snorm = (float*)(sm + OFF_SNORM);
    for (int i = tid; i < KCODES; i += NTHREADS) snorm[i] = g_enorm[i];

    // stage-load mapping: f = tid (0..511) -> (row, dim-quad) in blocked tile layout
    const int rowF = (tid >> 5) * 8 + (tid & 7);
    const int kbF  = (tid >> 3) & 3;
    const uint32_t soF = (uint32_t)tid * 16;

    // ldmatrix lane offsets (same fragment layout as validated in R6)
    const uint32_t aoff = ((lane >> 3) & 1) * 512 + (lane >> 4) * 128 + (lane & 7) * 16;
    const uint32_t boff = (lane >> 4) * 512 + ((lane >> 3) & 1) * 128 + (lane & 7) * 16;

    float minv[4];
    int   mini[4];
    #pragma unroll
    for (int i = 0; i < 4; i++) { minv[i] = FLT_MAX; mini[i] = 0; }

    #pragma unroll 1
    for (int c = 0; c < NCHUNK; c++) {
        const int cbase = c * CN;
        float acc[2][4][4];
        #pragma unroll
        for (int mt = 0; mt < 2; mt++)
            #pragma unroll
            for (int nt = 0; nt < 4; nt++)
                #pragma unroll
                for (int q = 0; q < 4; q++) acc[mt][nt][q] = 0.0f;

        __syncthreads();   // previous chunk fully done with tiles

        // --- stage 0: direct copy from pre-split arrays ---
        {
            const size_t ax = (size_t)(r0 + rowF) * DIM + kbF * 4;
            const size_t bx = (size_t)(cbase + rowF) * DIM + kbF * 4;
            *(uint4*)(sm + OFF_AH + soF) = *(const uint4*)(g_xh + ax);
            *(uint4*)(sm + OFF_AL + soF) = *(const uint4*)(g_xl + ax);
            *(uint4*)(sm + OFF_BH + soF) = *(const uint4*)(g_cbh + bx);
            *(uint4*)(sm + OFF_BL + soF) = *(const uint4*)(g_cbl + bx);
        }
        __syncthreads();

        int buf = 0;
        #pragma unroll 1
        for (int s = 0; s < NST; s++) {
            uint4 pah, pal, pbh, pbl;
            if (s < NST - 1) {
                const int d0 = (s + 1) * KS;
                const size_t ax = (size_t)(r0 + rowF) * DIM + d0 + kbF * 4;
                const size_t bx = (size_t)(cbase + rowF) * DIM + d0 + kbF * 4;
                pah = *(const uint4*)(g_xh + ax);
                pal = *(const uint4*)(g_xl + ax);
                pbh = *(const uint4*)(g_cbh + bx);
                pbl = *(const uint4*)(g_cbl + bx);
            }

            const uint32_t ahb = sb + OFF_AH + (uint32_t)buf * BUFSTRIDE;
            const uint32_t alb = sb + OFF_AL + (uint32_t)buf * BUFSTRIDE;
            const uint32_t bhb = sb + OFF_BH + (uint32_t)buf * BUFSTRIDE;
            const uint32_t blb = sb + OFF_BL + (uint32_t)buf * BUFSTRIDE;

            #pragma unroll
            for (int kk = 0; kk < 2; kk++) {
                uint32_t ah[2][4], al[2][4], bh[2][4], bl[2][4];
                #pragma unroll
                for (int mt = 0; mt < 2; mt++) {
                    const uint32_t tb = (uint32_t)((wm * 4 + mt * 2) * 512 + kk * 256);
                    ldm4(ah[mt], ahb + tb + aoff);
                    ldm4(al[mt], alb + tb + aoff);
                }
                #pragma unroll
                for (int np = 0; np < 2; np++) {
                    const uint32_t tb = (uint32_t)((wn * 4 + np * 2) * 512 + kk * 256);
                    ldm4(bh[np], bhb + tb + boff);
                    ldm4(bl[np], blb + tb + boff);
                }
                // product-major passes: same-acc revisit distance = 8 MMAs.
                // Per-accumulator order (hh, hl, lh, ll per kk) identical to R6 -> bit-identical.
                #pragma unroll
                for (int mt = 0; mt < 2; mt++)
                    #pragma unroll
                    for (int np = 0; np < 2; np++) {
                        mma8(acc[mt][np * 2],     ah[mt], bh[np][0], bh[np][1]);
                        mma8(acc[mt][np * 2 + 1], ah[mt], bh[np][2], bh[np][3]);
                    }
                #pragma unroll
                for (int mt = 0; mt < 2; mt++)
                    #pragma unroll
                    for (int np = 0; np < 2; np++) {
                        mma8(acc[mt][np * 2],     ah[mt], bl[np][0], bl[np][1]);
                        mma8(acc[mt][np * 2 + 1], ah[mt], bl[np][2], bl[np][3]);
                    }
                #pragma unroll
                for (int mt = 0; mt < 2; mt++)
                    #pragma unroll
                    for (int np = 0; np < 2; np++) {
                        mma8(acc[mt][np * 2],     al[mt], bh[np][0], bh[np][1]);
                        mma8(acc[mt][np * 2 + 1], al[mt], bh[np][2], bh[np][3]);
                    }
                #pragma unroll
                for (int mt = 0; mt < 2; mt++)
                    #pragma unroll
                    for (int np = 0; np < 2; np++) {
                        mma8(acc[mt][np * 2],     al[mt], bl[np][0], bl[np][1]);
                        mma8(acc[mt][np * 2 + 1], al[mt], bl[np][2], bl[np][3]);
                    }
            }

            if (s < NST - 1) {
                const int nb = buf ^ 1;
                *(uint4*)(sm + OFF_AH + nb * BUFSTRIDE + soF) = pah;
                *(uint4*)(sm + OFF_AL + nb * BUFSTRIDE + soF) = pal;
                *(uint4*)(sm + OFF_BH + nb * BUFSTRIDE + soF) = pbh;
                *(uint4*)(sm + OFF_BL + nb * BUFSTRIDE + soF) = pbl;
                __syncthreads();
                buf = nb;
            }
        }

        // --- chunk epilogue: dist = ||e||^2 - 2 x.e ; running argmin (codes ascending per thread) ---
        #pragma unroll
        for (int nt = 0; nt < 4; nt++) {
            const int code0 = cbase + wn * 32 + nt * 8 + 2 * (lane & 3);
            const float en0 = snorm[code0];
            const float en1 = snorm[code0 + 1];
            #pragma unroll
            for (int mt = 0; mt < 2; mt++) {
                const float* a = acc[mt][nt];
                const int s0 = mt * 2, s1 = mt * 2 + 1;
                float d;
                d = en0 - 2.0f * a[0]; if (d < minv[s0]) { minv[s0] = d; mini[s0] = code0; }
                d = en1 - 2.0f * a[1]; if (d < minv[s0]) { minv[s0] = d; mini[s0] = code0 + 1; }
                d = en0 - 2.0f * a[2]; if (d < minv[s1]) { minv[s1] = d; mini[s1] = code0; }
                d = en1 - 2.0f * a[3]; if (d < minv[s1]) { minv[s1] = d; mini[s1] = code0 + 1; }
            }
        }
    }

    // --- reduce: lanes sharing a row (lane%4 group), then across 4 wn columns via smem ---
    float* sredv = (float*)(sm + OFF_SREDV);
    int*   sredi = (int*)(sm + OFF_SREDI);
    #pragma unroll
    for (int sl = 0; sl < 4; sl++) {
        float v = minv[sl];
        int   id = mini[sl];
        #pragma unroll
        for (int o = 1; o <= 2; o <<= 1) {
            const float ov = __shfl_xor_sync(0xffffffffu, v, o);
            const int   oi = __shfl_xor_sync(0xffffffffu, id, o);
            if (ov < v || (ov == v && oi < id)) { v = ov; id = oi; }
        }
        if ((lane & 3) == 0) {
            const int rowl = wm * 32 + (sl >> 1) * 16 + (sl & 1) * 8 + (lane >> 2);
            sredv[wn * 128 + rowl] = v;
            sredi[wn * 128 + rowl] = id;
        }
    }
    __syncthreads();
    int* sIdx = (int*)(sm + OFF_SIDX);
    if (tid < 128) {
        float v0 = sredv[tid];
        int   i0 = sredi[tid];
        #pragma unroll
        for (int w = 1; w < 4; w++) {
            const float v1 = sredv[w * 128 + tid];
            const int   i1 = sredi[w * 128 + tid];
            if (v1 < v0 || (v1 == v0 && i1 < i0)) { v0 = v1; i0 = i1; }
        }
        sIdx[tid] = i0;
    }
    __syncthreads();

    // --- gather e[idx] rows (L2-resident) and write outputs ---
    const float4* cb4  = reinterpret_cast<const float4*>(cb);
    float4*       out4 = reinterpret_cast<float4*>(outq);
    #pragma unroll 4
    for (int f = tid; f < RN * DIM / 4; f += NTHREADS) {
        const int row  = f >> 6;
        const int cc   = f & 63;
        const int code = sIdx[row];
        out4[(size_t)(r0 + row) * (DIM / 4) + cc] = cb4[(size_t)code * (DIM / 4) + cc];
    }
    if (has_idx && tid < RN) outidx[r0 + tid] = (float)sIdx[tid];
}

extern "C" void kernel_launch(void* const* d_in, const int* in_sizes, int n_in,
                              void* d_out, int out_size) {
    const float* x  = (const float*)d_in[0];   // [65536, 256]
    const float* cb = (const float*)d_in[1];   // [1024, 256]
    float* outq = (float*)d_out;

    const int qElems = N_ROWS * DIM;
    const int has_idx = (out_size >= qElems + N_ROWS) ? 1 : 0;
    float* outidx = outq + qElems;

    cudaFuncSetAttribute(vq_kernel, cudaFuncAttributeMaxDynamicSharedMemorySize, SMEM_BYTES);

    prep_cb_kernel<<<KCODES, 64>>>(cb);
    prep_x_kernel<<<N_ROWS * DIM / 4 / 256, 256>>>(x);
    vq_kernel<<<N_ROWS / RN, NTHREADS, SMEM_BYTES>>>(cb, outq, outidx, has_idx);
}

// round 8
// speedup vs baseline: 1.2181x; 1.2181x over previous
#include <cuda_runtime.h>
#include <cfloat>
#include <cstdint>

// Problem: x [65536, 256] fp32, codebook [1024, 256] fp32. Nearest code per row.
#define N_ROWS  65536
#define DIM     256
#define KCODES  1024
#define RN      128     // rows per CTA
#define CN      128     // codes per chunk
#define NCHUNK  (KCODES / CN)
#define KS      16      // dims per stage
#define NST     (DIM / KS)
#define NTHREADS 256

// smem byte offsets (each tile region: 2 buffers x 8192B)
#define OFF_AH     0
#define OFF_AL     16384
#define OFF_BH     32768
#define OFF_BL     49152
#define OFF_SNORM  65536
#define OFF_SREDV  69632
#define OFF_SREDI  70656
#define OFF_SIDX   71680
#define SMEM_BYTES 72192
#define BUFSTRIDE  8192

__device__ float    g_enorm[KCODES];
__device__ uint32_t g_cbh[KCODES * DIM];   // pre-split tf32 hi of codebook (L2-resident, 2MB)
__device__ uint32_t g_cbl[KCODES * DIM];   // pre-split tf32 lo

__device__ __forceinline__ uint32_t smem_u32(const void* p) {
    uint32_t a;
    asm("{ .reg .u64 t; cvta.to.shared.u64 t, %1; cvt.u32.u64 %0, t; }" : "=r"(a) : "l"(p));
    return a;
}

__device__ __forceinline__ void split1(float v, uint32_t& h, uint32_t& l) {
    uint32_t hb; asm("cvt.rna.tf32.f32 %0, %1;" : "=r"(hb) : "f"(v));
    float lf = v - __uint_as_float(hb);
    uint32_t lb; asm("cvt.rna.tf32.f32 %0, %1;" : "=r"(lb) : "f"(lf));
    h = hb; l = lb;
}
__device__ __forceinline__ void split4(float4 v, uint4& h, uint4& l) {
    split1(v.x, h.x, l.x); split1(v.y, h.y, l.y);
    split1(v.z, h.z, l.z); split1(v.w, h.w, l.w);
}

__device__ __forceinline__ void ldm4(uint32_t* r, uint32_t addr) {
    asm volatile("ldmatrix.sync.aligned.m8n8.x4.shared.b16 {%0,%1,%2,%3}, [%4];"
                 : "=r"(r[0]), "=r"(r[1]), "=r"(r[2]), "=r"(r[3]) : "r"(addr));
}

__device__ __forceinline__ void mma8(float* c, const uint32_t* a, uint32_t b0, uint32_t b1) {
    asm volatile(
        "mma.sync.aligned.m16n8k8.row.col.f32.tf32.tf32.f32 "
        "{%0,%1,%2,%3}, {%4,%5,%6,%7}, {%8,%9}, {%0,%1,%2,%3};"
        : "+f"(c[0]), "+f"(c[1]), "+f"(c[2]), "+f"(c[3])
        : "r"(a[0]), "r"(a[1]), "r"(a[2]), "r"(a[3]), "r"(b0), "r"(b1));
}

__device__ __forceinline__ void cpa16(uint32_t saddr, const void* g) {
    asm volatile("cp.async.cg.shared.global [%0], [%1], 16;" :: "r"(saddr), "l"(g) : "memory");
}
#define CPA_COMMIT() asm volatile("cp.async.commit_group;" ::: "memory")
#define CPA_WAIT0()  asm volatile("cp.async.wait_group 0;" ::: "memory")

// --- pre-kernel: split codebook to tf32 hi/lo + codebook norms ---
__global__ void prep_cb_kernel(const float* __restrict__ cb) {
    const int code = blockIdx.x;
    const int t = threadIdx.x;                  // 64 threads, one float4 each
    const int i = code * (DIM / 4) + t;
    const float4 v = reinterpret_cast<const float4*>(cb)[i];
    uint4 h, l; split4(v, h, l);
    reinterpret_cast<uint4*>(g_cbh)[i] = h;
    reinterpret_cast<uint4*>(g_cbl)[i] = l;
    float s = v.x * v.x + v.y * v.y + v.z * v.z + v.w * v.w;
    #pragma unroll
    for (int o = 16; o > 0; o >>= 1) s += __shfl_down_sync(0xffffffffu, s, o);
    __shared__ float ws[2];
    if ((t & 31) == 0) ws[t >> 5] = s;
    __syncthreads();
    if (t == 0) g_enorm[code] = ws[0] + ws[1];
}

__global__ __launch_bounds__(NTHREADS, 1)
void vq_kernel(const float* __restrict__ x, const float* __restrict__ cb,
               float* __restrict__ outq, float* __restrict__ outidx, int has_idx)
{
    extern __shared__ char sm[];
    const uint32_t sb = smem_u32(sm);
    const int tid  = threadIdx.x;
    const int lane = tid & 31;
    const int wid  = tid >> 5;
    const int wm   = wid & 3;    // rows wm*32..+31
    const int wn   = wid >> 2;   // codes wn*64..+63 within chunk
    const int r0   = blockIdx.x * RN;

    float* snorm = (float*)(sm + OFF_SNORM);
    for (int i = tid; i < KCODES; i += NTHREADS) snorm[i] = g_enorm[i];

    // stage-load mapping: float4 f -> (row, dim-quad) in blocked tile layout (tile=f/8, r=f%8)
    const int f1 = tid, f2 = tid + 256;
    const int rowA1 = (f1 >> 5) * 8 + (f1 & 7), kb1 = (f1 >> 3) & 3;
    const int rowA2 = (f2 >> 5) * 8 + (f2 & 7), kb2 = (f2 >> 3) & 3;
    const uint32_t so1 = (uint32_t)f1 * 16, so2 = (uint32_t)f2 * 16;

    // ldmatrix lane offsets (fragment layout validated in R6)
    const uint32_t aoff = ((lane >> 3) & 1) * 512 + (lane >> 4) * 128 + (lane & 7) * 16;
    const uint32_t boff = (lane >> 4) * 512 + ((lane >> 3) & 1) * 128 + (lane & 7) * 16;

    float minv[4];
    int   mini[4];
    #pragma unroll
    for (int i = 0; i < 4; i++) { minv[i] = FLT_MAX; mini[i] = 0; }

    #pragma unroll 1
    for (int c = 0; c < NCHUNK; c++) {
        const int cbase = c * CN;
        float acc[2][8][4];
        #pragma unroll
        for (int mt = 0; mt < 2; mt++)
            #pragma unroll
            for (int nt = 0; nt < 8; nt++)
                #pragma unroll
                for (int q = 0; q < 4; q++) acc[mt][nt][q] = 0.0f;

        __syncthreads();   // previous chunk fully done with tiles

        // --- stage 0 load: B via cp.async from pre-split arrays, A load+split ---
        {
            const size_t bx1 = (size_t)(cbase + rowA1) * DIM + kb1 * 4;
            const size_t bx2 = (size_t)(cbase + rowA2) * DIM + kb2 * 4;
            cpa16(sb + OFF_BH + so1, g_cbh + bx1);
            cpa16(sb + OFF_BH + so2, g_cbh + bx2);
            cpa16(sb + OFF_BL + so1, g_cbl + bx1);
            cpa16(sb + OFF_BL + so2, g_cbl + bx2);
            CPA_COMMIT();
            const float4 a1 = *(const float4*)(x + (size_t)(r0 + rowA1) * DIM + kb1 * 4);
            const float4 a2 = *(const float4*)(x + (size_t)(r0 + rowA2) * DIM + kb2 * 4);
            uint4 h, l;
            split4(a1, h, l); *(uint4*)(sm + OFF_AH + so1) = h; *(uint4*)(sm + OFF_AL + so1) = l;
            split4(a2, h, l); *(uint4*)(sm + OFF_AH + so2) = h; *(uint4*)(sm + OFF_AL + so2) = l;
            CPA_WAIT0();
        }
        __syncthreads();

        int buf = 0;
        #pragma unroll 1
        for (int s = 0; s < NST; s++) {
            const int nb = buf ^ 1;
            float4 pa1, pa2;
            if (s < NST - 1) {
                const int d0 = (s + 1) * KS;
                // B prefetch: async, off the issue critical path
                const size_t bx1 = (size_t)(cbase + rowA1) * DIM + d0 + kb1 * 4;
                const size_t bx2 = (size_t)(cbase + rowA2) * DIM + d0 + kb2 * 4;
                cpa16(sb + OFF_BH + nb * BUFSTRIDE + so1, g_cbh + bx1);
                cpa16(sb + OFF_BH + nb * BUFSTRIDE + so2, g_cbh + bx2);
                cpa16(sb + OFF_BL + nb * BUFSTRIDE + so1, g_cbl + bx1);
                cpa16(sb + OFF_BL + nb * BUFSTRIDE + so2, g_cbl + bx2);
                CPA_COMMIT();
                pa1 = *(const float4*)(x + (size_t)(r0 + rowA1) * DIM + d0 + kb1 * 4);
                pa2 = *(const float4*)(x + (size_t)(r0 + rowA2) * DIM + d0 + kb2 * 4);
            }

            const uint32_t ahb = sb + OFF_AH + (uint32_t)buf * BUFSTRIDE;
            const uint32_t alb = sb + OFF_AL + (uint32_t)buf * BUFSTRIDE;
            const uint32_t bhb = sb + OFF_BH + (uint32_t)buf * BUFSTRIDE;
            const uint32_t blb = sb + OFF_BL + (uint32_t)buf * BUFSTRIDE;

            #pragma unroll
            for (int kk = 0; kk < 2; kk++) {
                uint32_t ah[2][4], al[2][4], bh[4][4], bl[4][4];
                #pragma unroll
                for (int mt = 0; mt < 2; mt++) {
                    const uint32_t tb = (uint32_t)((wm * 4 + mt * 2) * 512 + kk * 256);
                    ldm4(ah[mt], ahb + tb + aoff);
                    ldm4(al[mt], alb + tb + aoff);
                }
                #pragma unroll
                for (int np = 0; np < 4; np++) {
                    const uint32_t tb = (uint32_t)((wn * 8 + np * 2) * 512 + kk * 256);
                    ldm4(bh[np], bhb + tb + boff);
                    ldm4(bl[np], blb + tb + boff);
                }
                // product-major: same-acc revisit distance = 16 MMAs.
                // Per-accumulator order (hh, hl, lh, ll per kk) identical to R6 -> bit-identical.
                #pragma unroll
                for (int mt = 0; mt < 2; mt++)
                    #pragma unroll
                    for (int np = 0; np < 4; np++) {
                        mma8(acc[mt][np * 2],     ah[mt], bh[np][0], bh[np][1]);
                        mma8(acc[mt][np * 2 + 1], ah[mt], bh[np][2], bh[np][3]);
                    }
                #pragma unroll
                for (int mt = 0; mt < 2; mt++)
                    #pragma unroll
                    for (int np = 0; np < 4; np++) {
                        mma8(acc[mt][np * 2],     ah[mt], bl[np][0], bl[np][1]);
                        mma8(acc[mt][np * 2 + 1], ah[mt], bl[np][2], bl[np][3]);
                    }
                #pragma unroll
                for (int mt = 0; mt < 2; mt++)
                    #pragma unroll
                    for (int np = 0; np < 4; np++) {
                        mma8(acc[mt][np * 2],     al[mt], bh[np][0], bh[np][1]);
                        mma8(acc[mt][np * 2 + 1], al[mt], bh[np][2], bh[np][3]);
                    }
                #pragma unroll
                for (int mt = 0; mt < 2; mt++)
                    #pragma unroll
                    for (int np = 0; np < 4; np++) {
                        mma8(acc[mt][np * 2],     al[mt], bl[np][0], bl[np][1]);
                        mma8(acc[mt][np * 2 + 1], al[mt], bl[np][2], bl[np][3]);
                    }
            }

            if (s < NST - 1) {
                uint4 h, l;
                split4(pa1, h, l);
                *(uint4*)(sm + OFF_AH + nb * BUFSTRIDE + so1) = h;
                *(uint4*)(sm + OFF_AL + nb * BUFSTRIDE + so1) = l;
                split4(pa2, h, l);
                *(uint4*)(sm + OFF_AH + nb * BUFSTRIDE + so2) = h;
                *(uint4*)(sm + OFF_AL + nb * BUFSTRIDE + so2) = l;
                CPA_WAIT0();
                __syncthreads();
                buf = nb;
            }
        }

        // --- chunk epilogue: dist = ||e||^2 - 2 x.e ; running argmin (codes ascending per thread) ---
        #pragma unroll
        for (int nt = 0; nt < 8; nt++) {
            const int code0 = cbase + wn * 64 + nt * 8 + 2 * (lane & 3);
            const float en0 = snorm[code0];
            const float en1 = snorm[code0 + 1];
            #pragma unroll
            for (int mt = 0; mt < 2; mt++) {
                const float* a = acc[mt][nt];
                const int s0 = mt * 2, s1 = mt * 2 + 1;
                float d;
                d = en0 - 2.0f * a[0]; if (d < minv[s0]) { minv[s0] = d; mini[s0] = code0; }
                d = en1 - 2.0f * a[1]; if (d < minv[s0]) { minv[s0] = d; mini[s0] = code0 + 1; }
                d = en0 - 2.0f * a[2]; if (d < minv[s1]) { minv[s1] = d; mini[s1] = code0; }
                d = en1 - 2.0f * a[3]; if (d < minv[s1]) { minv[s1] = d; mini[s1] = code0 + 1; }
            }
        }
    }

    // --- reduce: lanes 4g..4g+3 share rows; tie -> smaller code ---
    float* sredv = (float*)(sm + OFF_SREDV);
    int*   sredi = (int*)(sm + OFF_SREDI);
    #pragma unroll
    for (int sl = 0; sl < 4; sl++) {
        float v = minv[sl];
        int   id = mini[sl];
        #pragma unroll
        for (int o = 1; o <= 2; o <<= 1) {
            const float ov = __shfl_xor_sync(0xffffffffu, v, o);
            const int   oi = __shfl_xor_sync(0xffffffffu, id, o);
            if (ov < v || (ov == v && oi < id)) { v = ov; id = oi; }
        }
        if ((lane & 3) == 0) {
            const int rowl = wm * 32 + (sl >> 1) * 16 + (sl & 1) * 8 + (lane >> 2);
            sredv[wn * 128 + rowl] = v;
            sredi[wn * 128 + rowl] = id;
        }
    }
    __syncthreads();
    int* sIdx = (int*)(sm + OFF_SIDX);
    if (tid < 128) {
        float v0 = sredv[tid];       int i0 = sredi[tid];
        const float v1 = sredv[128 + tid];
        const int   i1 = sredi[128 + tid];
        if (v1 < v0 || (v1 == v0 && i1 < i0)) { v0 = v1; i0 = i1; }
        sIdx[tid] = i0;
    }
    __syncthreads();

    // --- gather e[idx] rows and write outputs ---
    const float4* cb4  = reinterpret_cast<const float4*>(cb);
    float4*       out4 = reinterpret_cast<float4*>(outq);
    #pragma unroll 4
    for (int f = tid; f < RN * DIM / 4; f += NTHREADS) {
        const int row  = f >> 6;
        const int cc   = f & 63;
        const int code = sIdx[row];
        out4[(size_t)(r0 + row) * (DIM / 4) + cc] = cb4[(size_t)code * (DIM / 4) + cc];
    }
    if (has_idx && tid < RN) outidx[r0 + tid] = (float)sIdx[tid];
}

extern "C" void kernel_launch(void* const* d_in, const int* in_sizes, int n_in,
                              void* d_out, int out_size) {
    const float* x  = (const float*)d_in[0];   // [65536, 256]
    const float* cb = (const float*)d_in[1];   // [1024, 256]
    float* outq = (float*)d_out;

    const int qElems = N_ROWS * DIM;
    const int has_idx = (out_size >= qElems + N_ROWS) ? 1 : 0;
    float* outidx = outq + qElems;

    cudaFuncSetAttribute(vq_kernel, cudaFuncAttributeMaxDynamicSharedMemorySize, SMEM_BYTES);

    prep_cb_kernel<<<KCODES, 64>>>(cb);
    vq_kernel<<<N_ROWS / RN, NTHREADS, SMEM_BYTES>>>(x, cb, outq, outidx, has_idx);
}

// round 9
// speedup vs baseline: 1.3804x; 1.1332x over previous
#include <cuda_runtime.h>
#include <cfloat>
#include <cstdint>

// Problem: x [65536, 256] fp32, codebook [1024, 256] fp32. Nearest code per row.
#define N_ROWS  65536
#define DIM     256
#define KCODES  1024
#define RN      128     // rows per CTA
#define CN      64      // codes per chunk
#define NCHUNK  (KCODES / CN)
#define KS      16      // dims per stage
#define NST     (DIM / KS)
#define NTHREADS 256

// smem byte offsets: A tiles 2x8KB (hi,lo), B tiles 2x4KB (hi,lo)
#define OFF_AH     0
#define OFF_AL     16384
#define OFF_BH     32768
#define OFF_BL     40960
#define OFF_SNORM  49152
#define OFF_SREDV  53248
#define OFF_SREDI  54272
#define OFF_SIDX   55296
#define SMEM_BYTES 55808
#define ABUF       8192
#define BBUF       4096

__device__ float g_enorm[KCODES];

__device__ __forceinline__ uint32_t smem_u32(const void* p) {
    uint32_t a;
    asm("{ .reg .u64 t; cvta.to.shared.u64 t, %1; cvt.u32.u64 %0, t; }" : "=r"(a) : "l"(p));
    return a;
}

__device__ __forceinline__ void split1(float v, uint32_t& h, uint32_t& l) {
    uint32_t hb; asm("cvt.rna.tf32.f32 %0, %1;" : "=r"(hb) : "f"(v));
    float lf = v - __uint_as_float(hb);
    uint32_t lb; asm("cvt.rna.tf32.f32 %0, %1;" : "=r"(lb) : "f"(lf));
    h = hb; l = lb;
}
__device__ __forceinline__ void split4(float4 v, uint4& h, uint4& l) {
    split1(v.x, h.x, l.x); split1(v.y, h.y, l.y);
    split1(v.z, h.z, l.z); split1(v.w, h.w, l.w);
}

__device__ __forceinline__ void ldm4(uint32_t* r, uint32_t addr) {
    asm volatile("ldmatrix.sync.aligned.m8n8.x4.shared.b16 {%0,%1,%2,%3}, [%4];"
                 : "=r"(r[0]), "=r"(r[1]), "=r"(r[2]), "=r"(r[3]) : "r"(addr));
}

__device__ __forceinline__ void mma8(float* c, const uint32_t* a, uint32_t b0, uint32_t b1) {
    asm volatile(
        "mma.sync.aligned.m16n8k8.row.col.f32.tf32.tf32.f32 "
        "{%0,%1,%2,%3}, {%4,%5,%6,%7}, {%8,%9}, {%0,%1,%2,%3};"
        : "+f"(c[0]), "+f"(c[1]), "+f"(c[2]), "+f"(c[3])
        : "r"(a[0]), "r"(a[1]), "r"(a[2]), "r"(a[3]), "r"(b0), "r"(b1));
}

__global__ void enorm_kernel(const float* __restrict__ cb) {
    int code = blockIdx.x;
    int t = threadIdx.x;  // 64 threads, one float4 each
    const float4* row = reinterpret_cast<const float4*>(cb + (size_t)code * DIM);
    float4 v = row[t];
    float s = v.x * v.x + v.y * v.y + v.z * v.z + v.w * v.w;
    #pragma unroll
    for (int o = 16; o > 0; o >>= 1) s += __shfl_down_sync(0xffffffffu, s, o);
    __shared__ float ws[2];
    if ((t & 31) == 0) ws[t >> 5] = s;
    __syncthreads();
    if (t == 0) g_enorm[code] = ws[0] + ws[1];
}

__global__ __launch_bounds__(NTHREADS, 2)
void vq_kernel(const float* __restrict__ x, const float* __restrict__ cb,
               float* __restrict__ outq, float* __restrict__ outidx, int has_idx)
{
    extern __shared__ char sm[];
    const uint32_t sb = smem_u32(sm);
    const int tid  = threadIdx.x;
    const int lane = tid & 31;
    const int wid  = tid >> 5;
    const int wm   = wid & 3;    // rows wm*32..+31
    const int wn   = wid >> 2;   // codes wn*32..+31 within chunk
    const int r0   = blockIdx.x * RN;

    float* snorm = (float*)(sm + OFF_SNORM);
    for (int i = tid; i < KCODES; i += NTHREADS) snorm[i] = g_enorm[i];

    // A stage-load mapping: float4 f -> (row, dim-quad) in blocked tile layout (tile=f/8, r=f%8)
    const int f1 = tid, f2 = tid + 256;
    const int rowA1 = (f1 >> 5) * 8 + (f1 & 7), kb1 = (f1 >> 3) & 3;
    const int rowA2 = (f2 >> 5) * 8 + (f2 & 7), kb2 = (f2 >> 3) & 3;
    const uint32_t so1 = (uint32_t)f1 * 16, so2 = (uint32_t)f2 * 16;
    // B stage-load mapping: 256 float4 total (64 codes x 16 dims), 1 per thread
    const int rowB = rowA1, kbB = kb1;
    const uint32_t soB = so1;

    // ldmatrix lane offsets (fragment layout validated in R6)
    const uint32_t aoff = ((lane >> 3) & 1) * 512 + (lane >> 4) * 128 + (lane & 7) * 16;
    const uint32_t boff = (lane >> 4) * 512 + ((lane >> 3) & 1) * 128 + (lane & 7) * 16;

    float minv[4];
    int   mini[4];
    #pragma unroll
    for (int i = 0; i < 4; i++) { minv[i] = FLT_MAX; mini[i] = 0; }

    #pragma unroll 1
    for (int c = 0; c < NCHUNK; c++) {
        const int cbase = c * CN;
        float acc[2][4][4];
        #pragma unroll
        for (int mt = 0; mt < 2; mt++)
            #pragma unroll
            for (int nt = 0; nt < 4; nt++)
                #pragma unroll
                for (int q = 0; q < 4; q++) acc[mt][nt][q] = 0.0f;

        __syncthreads();   // previous chunk fully done with tiles

        // --- stage 0 load ---
        {
            const float4 a1 = *(const float4*)(x  + (size_t)(r0 + rowA1) * DIM + kb1 * 4);
            const float4 a2 = *(const float4*)(x  + (size_t)(r0 + rowA2) * DIM + kb2 * 4);
            const float4 b1 = *(const float4*)(cb + (size_t)(cbase + rowB) * DIM + kbB * 4);
            uint4 h, l;
            split4(a1, h, l); *(uint4*)(sm + OFF_AH + so1) = h; *(uint4*)(sm + OFF_AL + so1) = l;
            split4(a2, h, l); *(uint4*)(sm + OFF_AH + so2) = h; *(uint4*)(sm + OFF_AL + so2) = l;
            split4(b1, h, l); *(uint4*)(sm + OFF_BH + soB) = h; *(uint4*)(sm + OFF_BL + soB) = l;
        }
        __syncthreads();

        int buf = 0;
        #pragma unroll 1
        for (int s = 0; s < NST; s++) {
            float4 pa1, pa2, pb1;
            if (s < NST - 1) {
                const int d0 = (s + 1) * KS;
                pa1 = *(const float4*)(x  + (size_t)(r0 + rowA1) * DIM + d0 + kb1 * 4);
                pa2 = *(const float4*)(x  + (size_t)(r0 + rowA2) * DIM + d0 + kb2 * 4);
                pb1 = *(const float4*)(cb + (size_t)(cbase + rowB) * DIM + d0 + kbB * 4);
            }

            const uint32_t ahb = sb + OFF_AH + (uint32_t)buf * ABUF;
            const uint32_t alb = sb + OFF_AL + (uint32_t)buf * ABUF;
            const uint32_t bhb = sb + OFF_BH + (uint32_t)buf * BBUF;
            const uint32_t blb = sb + OFF_BL + (uint32_t)buf * BBUF;

            #pragma unroll
            for (int kk = 0; kk < 2; kk++) {
                uint32_t ah[2][4], al[2][4];
                #pragma unroll
                for (int mt = 0; mt < 2; mt++) {
                    const uint32_t tb = (uint32_t)((wm * 4 + mt * 2) * 512 + kk * 256);
                    ldm4(ah[mt], ahb + tb + aoff);
                    ldm4(al[mt], alb + tb + aoff);
                }
                #pragma unroll
                for (int np = 0; np < 2; np++) {
                    uint32_t bh[4], bl[4];
                    const uint32_t tb = (uint32_t)((wn * 4 + np * 2) * 512 + kk * 256);
                    ldm4(bh, bhb + tb + boff);
                    ldm4(bl, blb + tb + boff);
                    // per-acc order: hh, hl, lh, ll (bit-identical to R6);
                    // cross-acc interleave for ILP (revisit distance 4)
                    mma8(acc[0][np * 2],     ah[0], bh[0], bh[1]);
                    mma8(acc[0][np * 2 + 1], ah[0], bh[2], bh[3]);
                    mma8(acc[1][np * 2],     ah[1], bh[0], bh[1]);
                    mma8(acc[1][np * 2 + 1], ah[1], bh[2], bh[3]);
                    mma8(acc[0][np * 2],     ah[0], bl[0], bl[1]);
                    mma8(acc[0][np * 2 + 1], ah[0], bl[2], bl[3]);
                    mma8(acc[1][np * 2],     ah[1], bl[0], bl[1]);
                    mma8(acc[1][np * 2 + 1], ah[1], bl[2], bl[3]);
                    mma8(acc[0][np * 2],     al[0], bh[0], bh[1]);
                    mma8(acc[0][np * 2 + 1], al[0], bh[2], bh[3]);
                    mma8(acc[1][np * 2],     al[1], bh[0], bh[1]);
                    mma8(acc[1][np * 2 + 1], al[1], bh[2], bh[3]);
                    mma8(acc[0][np * 2],     al[0], bl[0], bl[1]);
                    mma8(acc[0][np * 2 + 1], al[0], bl[2], bl[3]);
                    mma8(acc[1][np * 2],     al[1], bl[0], bl[1]);
                    mma8(acc[1][np * 2 + 1], al[1], bl[2], bl[3]);
                }
            }

            if (s < NST - 1) {
                const int nb = buf ^ 1;
                uint4 h, l;
                split4(pa1, h, l);
                *(uint4*)(sm + OFF_AH + nb * ABUF + so1) = h;
                *(uint4*)(sm + OFF_AL + nb * ABUF + so1) = l;
                split4(pa2, h, l);
                *(uint4*)(sm + OFF_AH + nb * ABUF + so2) = h;
                *(uint4*)(sm + OFF_AL + nb * ABUF + so2) = l;
                split4(pb1, h, l);
                *(uint4*)(sm + OFF_BH + nb * BBUF + soB) = h;
                *(uint4*)(sm + OFF_BL + nb * BBUF + soB) = l;
                __syncthreads();
                buf = nb;
            }
        }

        // --- chunk epilogue: dist = ||e||^2 - 2 x.e ; running argmin (codes ascending per thread) ---
        #pragma unroll
        for (int nt = 0; nt < 4; nt++) {
            const int code0 = cbase + wn * 32 + nt * 8 + 2 * (lane & 3);
            const float en0 = snorm[code0];
            const float en1 = snorm[code0 + 1];
            #pragma unroll
            for (int mt = 0; mt < 2; mt++) {
                const float* a = acc[mt][nt];
                const int s0 = mt * 2, s1 = mt * 2 + 1;
                float d;
                d = en0 - 2.0f * a[0]; if (d < minv[s0]) { minv[s0] = d; mini[s0] = code0; }
                d = en1 - 2.0f * a[1]; if (d < minv[s0]) { minv[s0] = d; mini[s0] = code0 + 1; }
                d = en0 - 2.0f * a[2]; if (d < minv[s1]) { minv[s1] = d; mini[s1] = code0; }
                d = en1 - 2.0f * a[3]; if (d < minv[s1]) { minv[s1] = d; mini[s1] = code0 + 1; }
            }
        }
    }

    // --- reduce: lanes 4g..4g+3 share rows; tie -> smaller code ---
    float* sredv = (float*)(sm + OFF_SREDV);
    int*   sredi = (int*)(sm + OFF_SREDI);
    #pragma unroll
    for (int sl = 0; sl < 4; sl++) {
        float v = minv[sl];
        int   id = mini[sl];
        #pragma unroll
        for (int o = 1; o <= 2; o <<= 1) {
            const float ov = __shfl_xor_sync(0xffffffffu, v, o);
            const int   oi = __shfl_xor_sync(0xffffffffu, id, o);
            if (ov < v || (ov == v && oi < id)) { v = ov; id = oi; }
        }
        if ((lane & 3) == 0) {
            const int rowl = wm * 32 + (sl >> 1) * 16 + (sl & 1) * 8 + (lane >> 2);
            sredv[wn * 128 + rowl] = v;
            sredi[wn * 128 + rowl] = id;
        }
    }
    __syncthreads();
    int* sIdx = (int*)(sm + OFF_SIDX);
    if (tid < 128) {
        float v0 = sredv[tid];       int i0 = sredi[tid];
        const float v1 = sredv[128 + tid];
        const int   i1 = sredi[128 + tid];
        if (v1 < v0 || (v1 == v0 && i1 < i0)) { v0 = v1; i0 = i1; }
        sIdx[tid] = i0;
    }
    __syncthreads();

    // --- gather e[idx] rows and write outputs ---
    const float4* cb4  = reinterpret_cast<const float4*>(cb);
    float4*       out4 = reinterpret_cast<float4*>(outq);
    #pragma unroll 4
    for (int f = tid; f < RN * DIM / 4; f += NTHREADS) {
        const int row  = f >> 6;
        const int cc   = f & 63;
        const int code = sIdx[row];
        out4[(size_t)(r0 + row) * (DIM / 4) + cc] = cb4[(size_t)code * (DIM / 4) + cc];
    }
    if (has_idx && tid < RN) outidx[r0 + tid] = (float)sIdx[tid];
}

extern "C" void kernel_launch(void* const* d_in, const int* in_sizes, int n_in,
                              void* d_out, int out_size) {
    const float* x  = (const float*)d_in[0];   // [65536, 256]
    const float* cb = (const float*)d_in[1];   // [1024, 256]
    float* outq = (float*)d_out;

    const int qElems = N_ROWS * DIM;
    const int has_idx = (out_size >= qElems + N_ROWS) ? 1 : 0;
    float* outidx = outq + qElems;

    cudaFuncSetAttribute(vq_kernel, cudaFuncAttributeMaxDynamicSharedMemorySize, SMEM_BYTES);

    enorm_kernel<<<KCODES, 64>>>(cb);
    vq_kernel<<<N_ROWS / RN, NTHREADS, SMEM_BYTES>>>(x, cb, outq, outidx, has_idx);
}